// round 11
// baseline (speedup 1.0000x reference)
#include <cuda_runtime.h>
#include <cuda_fp16.h>
#include <cuda_fp8.h>
#include <math.h>
#include <stdint.h>

// ---------------- problem constants ----------------
#define NSAMP   1024
#define NCLS    9
#define PRE_K   512
#define DETS    100
#define IMGW    640.0f
#define IMGH    384.0f

#define O_EMB   ((size_t)0)
#define O_CLS   ((size_t)51380224)
#define O_REG   ((size_t)51389440)
#define O_BOX   ((size_t)51426304)
#define O_SCO   ((size_t)51427104)
#define O_LAB   ((size_t)51427304)
#define O_VAL   ((size_t)51427504)

// packed-M GEMM geometry: 1024 samples x 50 rows (49 valid + 1 pad), 400 m-tiles
#define MTILES 400

// ---------------- scratch (device globals; no allocation) ----------------
#define XN ((size_t)1024*512*56)
#define HN ((size_t)1024*1024*56)
__device__ __align__(16) __half g_x16r [XN + 128];
__device__ __align__(16) __half g_x16lr[XN + 128];
__device__ __align__(16) __half g_x16sr[XN + 128];     // shifted by +1 half
__device__ __align__(16) __half g_x16lsr[XN + 128];
__device__ __align__(16) __half g_h16r [HN + 128];
__device__ __align__(16) __half g_h16lr[HN + 128];
__device__ __align__(16) __half g_h16sr[HN + 128];
__device__ __align__(16) __half g_h16lsr[HN + 128];
#define X16  (g_x16r  + 64)
#define X16L (g_x16lr + 64)
#define X16S (g_x16sr + 64)
#define X16LS (g_x16lsr + 64)
#define H16  (g_h16r  + 64)
#define H16L (g_h16lr + 64)
#define H16S (g_h16sr + 64)
#define H16LS (g_h16lsr + 64)

// A^T hi tiles: tile (kc, mt) = 64 kk-rows x 272B = 17408 B
__device__ __align__(16) __half g_A1h[(size_t)72 *MTILES*8704];
__device__ __align__(16) __half g_A2h[(size_t)152*MTILES*8704];
// A^T fp8 tiles: A8 (32 kkpair-rows x 272B = 8704) + Al8 (8704) = 17408 B per tile
__device__ __align__(16) unsigned char g_A1q[(size_t)72 *MTILES*17408];
__device__ __align__(16) unsigned char g_A2q[(size_t)152*MTILES*17408];

// B hi tiles: (kc, nt) = 128 co-rows x 144B = 18432 B
__device__ __align__(16) __half g_w1h[(size_t)72 *8*9216];
__device__ __align__(16) __half g_wbh[(size_t)152*8*9216];
// B fp8 tiles: B8 (128 x 80B = 10240) + Bl8 (10240) = 20480 B per tile
__device__ __align__(16) unsigned char g_w1q[(size_t)72 *8*20480];
__device__ __align__(16) unsigned char g_wbq[(size_t)152*8*20480];

__device__ uint32_t g_mask[9][25];

__device__ float g_flat[(size_t)NSAMP*1024];
__device__ float g_cls[NSAMP*NCLS];
__device__ float g_reg[NSAMP*NCLS*4];
__device__ float g_boxes[NSAMP*NCLS*4];
__device__ float g_scores[NSAMP*NCLS];

// ================= PTX helpers =================
__device__ __forceinline__ uint32_t smem_u32(const void* p) {
    uint32_t a;
    asm("{ .reg .u64 t; cvta.to.shared.u64 t, %1; cvt.u32.u64 %0, t; }" : "=r"(a) : "l"(p));
    return a;
}
__device__ __forceinline__ void cp_bulk(uint32_t dst, const void* src, uint32_t bytes,
                                        uint32_t mbar) {
    asm volatile(
        "cp.async.bulk.shared::cluster.global.mbarrier::complete_tx::bytes [%0], [%1], %2, [%3];"
        :: "r"(dst), "l"(src), "r"(bytes), "r"(mbar) : "memory");
}
#define MBAR_INIT(mb, n) asm volatile("mbarrier.init.shared.b64 [%0], %1;" :: "r"(mb), "r"(n) : "memory")
#define MBAR_EXPECT(mb, tx) asm volatile("mbarrier.arrive.expect_tx.shared.b64 _, [%0], %1;" :: "r"(mb), "r"(tx) : "memory")
#define FENCE_ASYNC() asm volatile("fence.proxy.async.shared::cta;" ::: "memory")
__device__ __forceinline__ void mbar_wait(uint32_t mb, uint32_t parity) {
    asm volatile(
        "{\n\t.reg .pred P;\n\t"
        "W%=:\n\tmbarrier.try_wait.parity.acquire.cta.shared::cta.b64 P, [%0], %1, 0x989680;\n\t"
        "@!P bra W%=;\n\t}"
        :: "r"(mb), "r"(parity) : "memory");
}

__device__ __forceinline__ void ldm_x4(uint32_t* r, uint32_t a) {
    asm volatile("ldmatrix.sync.aligned.m8n8.x4.shared.b16 {%0,%1,%2,%3}, [%4];"
        : "=r"(r[0]), "=r"(r[1]), "=r"(r[2]), "=r"(r[3]) : "r"(a));
}
__device__ __forceinline__ void ldm_x4t(uint32_t* r, uint32_t a) {
    asm volatile("ldmatrix.sync.aligned.m8n8.x4.trans.shared.b16 {%0,%1,%2,%3}, [%4];"
        : "=r"(r[0]), "=r"(r[1]), "=r"(r[2]), "=r"(r[3]) : "r"(a));
}
__device__ __forceinline__ void mma16816(float* c, const uint32_t* a, uint32_t b0, uint32_t b1) {
    asm volatile(
        "mma.sync.aligned.m16n8k16.row.col.f32.f16.f16.f32 "
        "{%0,%1,%2,%3}, {%4,%5,%6,%7}, {%8,%9}, {%0,%1,%2,%3};"
        : "+f"(c[0]), "+f"(c[1]), "+f"(c[2]), "+f"(c[3])
        : "r"(a[0]), "r"(a[1]), "r"(a[2]), "r"(a[3]), "r"(b0), "r"(b1));
}
__device__ __forceinline__ void mma16832q(float* c, const uint32_t* a, uint32_t b0, uint32_t b1) {
    asm volatile(
        "mma.sync.aligned.m16n8k32.row.col.f32.e4m3.e4m3.f32 "
        "{%0,%1,%2,%3}, {%4,%5,%6,%7}, {%8,%9}, {%0,%1,%2,%3};"
        : "+f"(c[0]), "+f"(c[1]), "+f"(c[2]), "+f"(c[3])
        : "r"(a[0]), "r"(a[1]), "r"(a[2]), "r"(a[3]), "r"(b0), "r"(b1));
}
__device__ __forceinline__ unsigned char e4(float f) {
    return (unsigned char)__nv_cvt_float_to_fp8(f, __NV_SATFINITE, __NV_E4M3);
}

// ---------------- conversion / prep kernels ----------------
__global__ void cvt_x16(const float* __restrict__ x) {
    size_t i = (size_t)blockIdx.x * 256 + threadIdx.x;
    if (i >= XN) return;
    int p = (int)(i % 56);
    size_t row = i / 56;
    float v = (p < 49) ? x[row * 49 + p] : 0.f;
    __half hh = __float2half(v);
    X16[i]  = hh;
    X16L[i] = __float2half(v - __half2float(hh));
}
__global__ void shift_x() {
    size_t i = (size_t)blockIdx.x * 256 + threadIdx.x;
    if (i >= XN) return;
    X16S[i]  = X16[i + 1];
    X16LS[i] = X16L[i + 1];
}
__global__ void shift_h() {
    size_t i = (size_t)blockIdx.x * 256 + threadIdx.x;
    if (i >= HN) return;
    H16S[i]  = H16[i + 1];
    H16LS[i] = H16L[i + 1];
}
// weights -> tiled hi [kc][co 128 x 72 halves] + fp8 [kc][co 128 x 80B] (B8 | Bl8)
__global__ void cvt_w1h(const float* __restrict__ w) {
    size_t i = (size_t)blockIdx.x * 256 + threadIdx.x;
    if (i >= (size_t)1024*4608) return;
    int co = (int)(i / 4608);
    int kk = (int)(i - (size_t)co * 4608);
    float v = w[i];
    __half hh = __float2half(v);
    size_t t = (size_t)((kk >> 6) * 8 + (co >> 7));
    g_w1h[t * 9216 + (co & 127) * 72 + (kk & 63)] = hh;
    size_t qd = t * 20480 + (size_t)(co & 127) * 80 + (kk & 63);
    g_w1q[qd]         = e4(v);
    g_w1q[qd + 10240] = e4((v - __half2float(hh)) * 4096.f);
}
__global__ void cvt_wbh(const float* __restrict__ w2, const float* __restrict__ wd) {
    size_t i = (size_t)blockIdx.x * 256 + threadIdx.x;
    if (i >= (size_t)1024*9728) return;
    int co = (int)(i / 9728);
    int kk = (int)(i - (size_t)co * 9728);
    float v = (kk < 9216) ? w2[(size_t)co * 9216 + kk] : wd[(size_t)co * 512 + (kk - 9216)];
    __half hh = __float2half(v);
    size_t t = (size_t)((kk >> 6) * 8 + (co >> 7));
    g_wbh[t * 9216 + (co & 127) * 72 + (kk & 63)] = hh;
    size_t qd = t * 20480 + (size_t)(co & 127) * 80 + (kk & 63);
    g_wbq[qd]         = e4(v);
    g_wbq[qd + 10240] = e4((v - __half2float(hh)) * 4096.f);
}
__global__ void init_mask() {
    int t = threadIdx.x;
    if (t >= 225) return;
    int off = t / 25, w = t - (t / 25) * 25;
    int ky = off / 3, kx = off - (off / 3) * 3;
    uint32_t m = 0;
    #pragma unroll
    for (int h = 0; h < 2; h++) {
        int p = 2 * w + h;
        if (p < 49) {
            int y = p / 7, x = p - (p / 7) * 7;
            int yy = y + ky - 1, xx = x + kx - 1;
            if (yy >= 0 && yy < 7 && xx >= 0 && xx < 7) m |= 0xFFFFu << (16 * h);
        }
    }
    g_mask[off][w] = m;
}

// ---------------- im2col to tiled global A^T (fp16 hi + fp8 A8/Al8) ----------------
// one thread per (kkpair, n)
template<int P>
__global__ void im2col_kernel() {
    int idx = blockIdx.x * 256 + threadIdx.x;
    int n = idx & 1023;
    int r = idx >> 10;                       // kkpair
    const int KK = (P == 1) ? 4608 : 9728;
    if (2 * r >= KK) return;

    const uint32_t *srcA[2], *srcLA[2], *mkA[2];
    #pragma unroll
    for (int j = 0; j < 2; j++) {
        int kk = 2 * r + j;
        int ci, off; const __half *H, *Hs, *L, *Ls; int CI;
        if (P == 2 && kk >= 9216) {
            ci = kk - 9216; off = 4;
            H = X16; Hs = X16S; L = X16L; Ls = X16LS; CI = 512;
        } else {
            ci = kk / 9; off = kk - ci * 9;
            if (P == 1) { H = X16; Hs = X16S; L = X16L; Ls = X16LS; CI = 512; }
            else        { H = H16; Hs = H16S; L = H16L; Ls = H16LS; CI = 1024; }
        }
        int ky = off / 3, kx = off - ky * 3;
        int del = (ky - 1) * 7 + (kx - 1);
        int sh = del & 1, ws = (del - sh) >> 1;
        srcA[j]  = (const uint32_t*)((sh ? Hs : H) + (size_t)(n * CI + ci) * 56) + ws;
        srcLA[j] = (const uint32_t*)((sh ? Ls : L) + (size_t)(n * CI + ci) * 56) + ws;
        mkA[j] = g_mask[off];
    }
    uint32_t* dh_b = (uint32_t*)((P == 1) ? g_A1h : g_A2h);
    unsigned char* dq_b = (P == 1) ? g_A1q : g_A2q;
    int kc = r >> 5, rl = r & 31;
    int m0 = n * 50;
    #pragma unroll
    for (int w = 0; w < 25; w++) {
        int m = m0 + 2 * w;
        int mt = m >> 7, ml = m & 127;
        size_t tile = (size_t)(kc * MTILES + mt);
        uint32_t h0 = srcA[0][w] & mkA[0][w];
        uint32_t h1 = srcA[1][w] & mkA[1][w];
        uint32_t l0 = srcLA[0][w] & mkA[0][w];
        uint32_t l1 = srcLA[1][w] & mkA[1][w];
        dh_b[tile * 4352 + (size_t)(2 * rl)     * 68 + (ml >> 1)] = h0;
        dh_b[tile * 4352 + (size_t)(2 * rl + 1) * 68 + (ml >> 1)] = h1;
        float2 f0 = __half22float2(*(__half2*)&h0);
        float2 f1 = __half22float2(*(__half2*)&h1);
        float2 g0 = __half22float2(*(__half2*)&l0);
        float2 g1 = __half22float2(*(__half2*)&l1);
        uchar4 q  = make_uchar4(e4(f0.x), e4(f1.x), e4(f0.y), e4(f1.y));
        uchar4 ql = make_uchar4(e4(g0.x * 4096.f), e4(g1.x * 4096.f),
                                e4(g0.y * 4096.f), e4(g1.y * 4096.f));
        size_t qa = tile * 17408 + (size_t)rl * 272 + (size_t)ml * 2;
        *(uchar4*)(dq_b + qa)        = q;
        *(uchar4*)(dq_b + qa + 8704) = ql;
    }
}

// ---------------- split GEMM: fp16 main + fp8 corrections, TMA-fed ----------------
// smem per stage: Ah 17408, Aq 17408 (A8|Al8), Bh 18432, Bq 20480 (B8|Bl8)
#define AHO(st) ((uint32_t)(st) * 17408u)
#define AQO(st) (52224u + (uint32_t)(st) * 17408u)
#define BHO(st) (104448u + (uint32_t)(st) * 18432u)
#define BQO(st) (159744u + (uint32_t)(st) * 20480u)
#define MB_OFF  221184u
#define GSMEM   221216
#define CHUNK_TX 73728u

__device__ __forceinline__ void mma8h(float (*acc)[4], const uint32_t A[2][4],
                                      const uint32_t Q0[4], const uint32_t Q1[4]) {
    #pragma unroll
    for (int i = 0; i < 2; i++) {
        mma16816(acc[i*4+0], A[i], Q0[0], Q0[2]);
        mma16816(acc[i*4+1], A[i], Q0[1], Q0[3]);
        mma16816(acc[i*4+2], A[i], Q1[0], Q1[2]);
        mma16816(acc[i*4+3], A[i], Q1[1], Q1[3]);
    }
}
__device__ __forceinline__ void mma8q(float (*acc)[4], const uint32_t A[2][4],
                                      const uint32_t Q0[4], const uint32_t Q1[4]) {
    #pragma unroll
    for (int i = 0; i < 2; i++) {
        mma16832q(acc[i*4+0], A[i], Q0[0], Q0[2]);
        mma16832q(acc[i*4+1], A[i], Q0[1], Q0[3]);
        mma16832q(acc[i*4+2], A[i], Q1[0], Q1[2]);
        mma16832q(acc[i*4+3], A[i], Q1[1], Q1[3]);
    }
}

template<int P>
__global__ void __launch_bounds__(512, 1) gemm_conv(float* __restrict__ d_out) {
    extern __shared__ char smem[];
    const uint32_t sb = smem_u32(smem);
    const int tid  = threadIdx.x;
    const int lane = tid & 31;
    const int wid  = tid >> 5;                 // 16 warps
    const int wm   = wid >> 2, wn = wid & 3;   // 4x4 warp grid, 32x32 tiles
    const int nt   = blockIdx.x;               // 8 n-tiles
    const int mt   = blockIdx.y;               // 400 m-tiles

    const char* Ah_g = (const char*)((P == 1) ? g_A1h : g_A2h);
    const char* Aq_g = (const char*)((P == 1) ? g_A1q : g_A2q);
    const char* Bh_g = (const char*)((P == 1) ? g_w1h : g_wbh);
    const char* Bq_g = (const char*)((P == 1) ? g_w1q : g_wbq);
    const int NC = (P == 1) ? 72 : 152;

    if (tid == 0) {
        MBAR_INIT(sb + MB_OFF + 0, 1);
        MBAR_INIT(sb + MB_OFF + 8, 1);
        MBAR_INIT(sb + MB_OFF + 16, 1);
        FENCE_ASYNC();
    }
    __syncthreads();

    auto issue = [&](int c) {
        if (c < NC && tid == 0) {
            int st = c - (c / 3) * 3;
            uint32_t mb = sb + MB_OFF + (uint32_t)st * 8u;
            MBAR_EXPECT(mb, CHUNK_TX);
            cp_bulk(sb + AHO(st), Ah_g + ((size_t)c * MTILES + mt) * 17408, 17408u, mb);
            cp_bulk(sb + AQO(st), Aq_g + ((size_t)c * MTILES + mt) * 17408, 17408u, mb);
            cp_bulk(sb + BHO(st), Bh_g + ((size_t)c * 8 + nt) * 18432, 18432u, mb);
            cp_bulk(sb + BQO(st), Bq_g + ((size_t)c * 8 + nt) * 20480, 20480u, mb);
        }
    };

    float acc1[8][4], acc2[8][4];
    #pragma unroll
    for (int i = 0; i < 8; i++)
        #pragma unroll
        for (int e = 0; e < 4; e++) { acc1[i][e] = 0.f; acc2[i][e] = 0.f; }

    // same aRow for fp16 (row=kk, 272B) and fp8 (row=kkpair, 272B)
    const uint32_t aRow  = ((lane & 7) + ((lane >> 4) & 1) * 8) * 272u
                         + (uint32_t)(wm * 32 + ((lane >> 3) & 1) * 8) * 2u;
    const uint32_t bRow  = (uint32_t)(wn * 32 + (lane & 15)) * 144u + ((lane >> 4) & 1) * 16u;
    const uint32_t bRow8 = (uint32_t)(wn * 32 + (lane & 15)) * 80u  + ((lane >> 4) & 1) * 16u;

    issue(0); issue(1);

    for (int c = 0; c < NC; c++) {
        int st = c - (c / 3) * 3;
        mbar_wait(sb + MB_OFF + (uint32_t)st * 8u, (uint32_t)((c / 3) & 1));
        __syncthreads();                       // stage (c-1)%3 fully consumed
        issue(c + 2);                          // refill stage (c+2)%3 == (c-1)%3
        const uint32_t Ahs = sb + AHO(st), Aqs = sb + AQO(st);
        const uint32_t Bhs = sb + BHO(st), Bqs = sb + BQO(st);
        // fp16 main pass: Ah*Bh
        #pragma unroll
        for (int ks = 0; ks < 4; ks++) {
            uint32_t A[2][4], Q0[4], Q1[4];
            const uint32_t ao = aRow + (uint32_t)ks * (16u * 272u);
            const uint32_t bo = bRow + (uint32_t)ks * 32u;
            ldm_x4t(A[0], Ahs + ao);
            ldm_x4t(A[1], Ahs + ao + 32u);
            ldm_x4(Q0, Bhs + bo);
            ldm_x4(Q1, Bhs + bo + 16u * 144u);
            mma8h(&acc1[0], A, Q0, Q1);
        }
        // fp8 corrections: Al8*B8 + A8*Bl8 (scale 2^-12 folded in epilogue)
        #pragma unroll
        for (int k8 = 0; k8 < 2; k8++) {
            uint32_t F[2][4], Q0[4], Q1[4];
            const uint32_t ao = aRow + (uint32_t)k8 * (16u * 272u);
            const uint32_t bo = bRow8 + (uint32_t)k8 * 32u;
            ldm_x4t(F[0], Aqs + 8704u + ao);
            ldm_x4t(F[1], Aqs + 8704u + ao + 32u);
            ldm_x4(Q0, Bqs + bo);
            ldm_x4(Q1, Bqs + bo + 16u * 80u);
            mma8q(&acc2[0], F, Q0, Q1);        // Al8 * B8
            ldm_x4t(F[0], Aqs + ao);
            ldm_x4t(F[1], Aqs + ao + 32u);
            ldm_x4(Q0, Bqs + 10240u + bo);
            ldm_x4(Q1, Bqs + 10240u + bo + 16u * 80u);
            mma8q(&acc2[0], F, Q0, Q1);        // A8 * Bl8
        }
    }
    __syncthreads();

    // ---- epilogue: combine + relu, stage through smem [128 co][132 m] ----
    float* sf = (float*)smem;
    #pragma unroll
    for (int i = 0; i < 2; i++) {
        #pragma unroll
        for (int j = 0; j < 4; j++) {
            int m  = wm * 32 + i * 16 + (lane >> 2);
            int co = wn * 32 + j * 8 + ((lane & 3) << 1);
            const float* a = acc1[i*4+j];
            const float* b = acc2[i*4+j];
            sf[co * 132 + m]           = fmaxf(a[0] + 0.000244140625f * b[0], 0.f);
            sf[(co + 1) * 132 + m]     = fmaxf(a[1] + 0.000244140625f * b[1], 0.f);
            sf[co * 132 + m + 8]       = fmaxf(a[2] + 0.000244140625f * b[2], 0.f);
            sf[(co + 1) * 132 + m + 8] = fmaxf(a[3] + 0.000244140625f * b[3], 0.f);
        }
    }
    __syncthreads();
    for (int idx = tid; idx < 128 * 128; idx += 512) {
        int co_l = idx >> 7, ml = idx & 127;
        int m_g = mt * 128 + ml;
        int n = m_g / 50;
        int p = m_g - n * 50;
        if (p < 49) {
            float v = sf[co_l * 132 + ml];
            int co_g = nt * 128 + co_l;
            if (P == 1) {
                size_t o = ((size_t)(n * 1024 + co_g)) * 56 + p;
                __half hh = __float2half(v);
                H16[o]  = hh;
                H16L[o] = __float2half(v - __half2float(hh));
            } else {
                d_out[O_EMB + ((size_t)(n * 1024 + co_g)) * 49 + p] = v;
            }
        }
    }
}

// ---------------- avg pool ----------------
__global__ void flat_kernel(const float* __restrict__ emb) {
    int n = blockIdx.x;
    for (int co = threadIdx.x; co < 1024; co += 256) {
        const float* e = emb + ((size_t)n * 1024 + co) * 49;
        float s = 0.f;
        #pragma unroll
        for (int p = 0; p < 49; p++) s += e[p];
        g_flat[(size_t)n * 1024 + co] = s / 49.0f;
    }
}

// ---------------- head GEMMs ----------------
__global__ void head_kernel(const float* __restrict__ cls_w, const float* __restrict__ cls_b,
                            const float* __restrict__ reg_w, const float* __restrict__ reg_b,
                            float* __restrict__ d_out) {
    int n = blockIdx.x;
    int w = threadIdx.x >> 5, lane = threadIdx.x & 31;
    const float* f = g_flat + (size_t)n * 1024;
    for (int o = w; o < 45; o += 8) {
        const float* wr; float bias;
        if (o < NCLS) { wr = cls_w + (size_t)o * 1024; bias = cls_b[o]; }
        else          { wr = reg_w + (size_t)(o - NCLS) * 1024; bias = reg_b[o - NCLS]; }
        float acc = 0.f;
        for (int k = lane; k < 1024; k += 32) acc += f[k] * wr[k];
        #pragma unroll
        for (int d = 16; d; d >>= 1) acc += __shfl_xor_sync(0xffffffffu, acc, d);
        if (lane == 0) {
            float v = acc + bias;
            if (o < NCLS) { g_cls[n * NCLS + o] = v; d_out[O_CLS + n * NCLS + o] = v; }
            else { g_reg[n * 36 + (o - NCLS)] = v; d_out[O_REG + n * 36 + (o - NCLS)] = v; }
        }
    }
}

// ---------------- softmax + box decode + clip ----------------
__global__ void decode_kernel(const float* __restrict__ proposals) {
    int n = blockIdx.x; int lane = threadIdx.x;
    float logit = (lane < NCLS) ? g_cls[n * NCLS + lane] : -INFINITY;
    float m = logit;
    #pragma unroll
    for (int d = 16; d; d >>= 1) m = fmaxf(m, __shfl_xor_sync(0xffffffffu, m, d));
    float e = (lane < NCLS) ? expf(logit - m) : 0.f;
    float s = e;
    #pragma unroll
    for (int d = 16; d; d >>= 1) s += __shfl_xor_sync(0xffffffffu, s, d);
    if (lane < NCLS) {
        g_scores[n * NCLS + lane] = e / s;
        const float* pr = proposals + (size_t)n * 4;
        float pw = pr[2] - pr[0], ph = pr[3] - pr[1];
        float pcx = pr[0] + 0.5f * pw, pcy = pr[1] + 0.5f * ph;
        const float* rr = g_reg + n * 36 + lane * 4;
        float dx = rr[0] / 10.0f, dy = rr[1] / 10.0f;
        float dw = fminf(rr[2] / 5.0f, 4.135166556742356f);
        float dh = fminf(rr[3] / 5.0f, 4.135166556742356f);
        float ncx = dx * pw + pcx, ncy = dy * ph + pcy;
        float nw = expf(dw) * pw, nh = expf(dh) * ph;
        float b0 = fminf(fmaxf(ncx - 0.5f * nw, 0.f), IMGW);
        float b1 = fminf(fmaxf(ncy - 0.5f * nh, 0.f), IMGH);
        float b2 = fminf(fmaxf(ncx + 0.5f * nw, 0.f), IMGW);
        float b3 = fminf(fmaxf(ncy + 0.5f * nh, 0.f), IMGH);
        float* bp = g_boxes + (size_t)(n * NCLS + lane) * 4;
        bp[0] = b0; bp[1] = b1; bp[2] = b2; bp[3] = b3;
    }
}

// ---------------- per-image: filter -> sort(4096) -> NMS(512) -> top-100 ----------------
__global__ void __launch_bounds__(512) nms_kernel(float* __restrict__ d_out) {
    __shared__ float skey[4096];
    __shared__ int   sidx[4096];
    __shared__ float sbox[PRE_K * 4];
    __shared__ int   skeep[PRE_K];
    __shared__ int   swsum[16];

    int img = blockIdx.x; int tid = threadIdx.x;

    for (int j = tid; j < 4096; j += 512) {
        int p = j >> 3, c = (j & 7) + 1;
        int n = img * 512 + p;
        float s = g_scores[n * NCLS + c];
        const float* bb = g_boxes + (size_t)(n * NCLS + c) * 4;
        bool valid = (s > 0.05f) && ((bb[2] - bb[0]) >= 0.01f) && ((bb[3] - bb[1]) >= 0.01f);
        skey[j] = valid ? s : -INFINITY;
        sidx[j] = j;
    }
    __syncthreads();

    for (int k = 2; k <= 4096; k <<= 1) {
        for (int j2 = k >> 1; j2 > 0; j2 >>= 1) {
            for (int i = tid; i < 4096; i += 512) {
                int ixj = i ^ j2;
                if (ixj > i) {
                    float ka = skey[i], kb = skey[ixj];
                    int ia = sidx[i], ib = sidx[ixj];
                    bool a_first = (ka > kb) || (ka == kb && ia < ib);
                    bool up = ((i & k) == 0);
                    if (up ? !a_first : a_first) {
                        skey[i] = kb; skey[ixj] = ka;
                        sidx[i] = ib; sidx[ixj] = ia;
                    }
                }
            }
            __syncthreads();
        }
    }

    if (tid < PRE_K) {
        float s = skey[tid];
        int j = sidx[tid];
        int p = j >> 3, c = (j & 7) + 1;
        int n = img * 512 + p;
        const float* bb = g_boxes + (size_t)(n * NCLS + c) * 4;
        float off = 641.0f * (float)c;
        sbox[tid * 4 + 0] = bb[0] + off;
        sbox[tid * 4 + 1] = bb[1] + off;
        sbox[tid * 4 + 2] = bb[2] + off;
        sbox[tid * 4 + 3] = bb[3] + off;
        skeep[tid] = (s != -INFINITY) ? 1 : 0;
    }
    __syncthreads();

    for (int i = 0; i < PRE_K; i++) {
        if (skeep[i]) {
            int j = tid;
            if (j > i && skeep[j]) {
                float ax0 = sbox[i*4], ay0 = sbox[i*4+1], ax1 = sbox[i*4+2], ay1 = sbox[i*4+3];
                float bx0 = sbox[j*4], by0 = sbox[j*4+1], bx1 = sbox[j*4+2], by1 = sbox[j*4+3];
                float areaA = (ax1 - ax0) * (ay1 - ay0);
                float areaB = (bx1 - bx0) * (by1 - by0);
                float iw = fmaxf(fminf(ax1, bx1) - fmaxf(ax0, bx0), 0.f);
                float ih = fmaxf(fminf(ay1, by1) - fmaxf(ay0, by0), 0.f);
                float inter = iw * ih;
                float iou = inter / fmaxf(areaA + areaB - inter, 1e-8f);
                if (iou > 0.5f) skeep[j] = 0;
            }
        }
        __syncthreads();
    }

    int keepflag = (tid < PRE_K) ? skeep[tid] : 0;
    unsigned mask = __ballot_sync(0xffffffffu, keepflag != 0);
    int lane = tid & 31, wid = tid >> 5;
    if (lane == 0) swsum[wid] = __popc(mask);
    __syncthreads();
    int base = 0;
    for (int w = 0; w < wid; w++) base += swsum[w];
    int rank = base + __popc(mask & ((1u << lane) - 1u));

    float* dbx = d_out + O_BOX + (size_t)img * DETS * 4;
    float* dsc = d_out + O_SCO + (size_t)img * DETS;
    float* dlb = d_out + O_LAB + (size_t)img * DETS;
    float* dvl = d_out + O_VAL + (size_t)img * DETS;
    for (int i = tid; i < DETS; i += 512) {
        dbx[i*4+0] = 0.f; dbx[i*4+1] = 0.f; dbx[i*4+2] = 0.f; dbx[i*4+3] = 0.f;
        dsc[i] = 0.f; dlb[i] = 0.f; dvl[i] = 0.f;
    }
    __syncthreads();
    if (keepflag && rank < DETS) {
        int j = sidx[tid];
        int p = j >> 3, c = (j & 7) + 1;
        int n = img * 512 + p;
        const float* bb = g_boxes + (size_t)(n * NCLS + c) * 4;
        dbx[rank*4+0] = bb[0]; dbx[rank*4+1] = bb[1];
        dbx[rank*4+2] = bb[2]; dbx[rank*4+3] = bb[3];
        dsc[rank] = skey[tid];
        dlb[rank] = (float)c;
        dvl[rank] = 1.0f;
    }
}

// ---------------- launch ----------------
extern "C" void kernel_launch(void* const* d_in, const int* in_sizes, int n_in,
                              void* d_out, int out_size) {
    const float* feats     = (const float*)d_in[0];
    const float* proposals = (const float*)d_in[1];
    const float* w1        = (const float*)d_in[2];
    const float* w2        = (const float*)d_in[3];
    const float* wd        = (const float*)d_in[4];
    const float* cls_w     = (const float*)d_in[5];
    const float* cls_b     = (const float*)d_in[6];
    const float* reg_w     = (const float*)d_in[7];
    const float* reg_b     = (const float*)d_in[8];
    float* out = (float*)d_out;

    cudaFuncSetAttribute(gemm_conv<1>, cudaFuncAttributeMaxDynamicSharedMemorySize, GSMEM);
    cudaFuncSetAttribute(gemm_conv<2>, cudaFuncAttributeMaxDynamicSharedMemorySize, GSMEM);

    cvt_x16<<<(int)((XN + 255) / 256), 256>>>(feats);
    shift_x<<<(int)((XN + 255) / 256), 256>>>();
    cvt_w1h<<<(int)(((size_t)1024*4608 + 255) / 256), 256>>>(w1);
    cvt_wbh<<<(int)(((size_t)1024*9728 + 255) / 256), 256>>>(w2, wd);
    init_mask<<<1, 256>>>();

    im2col_kernel<1><<<2304 * 4, 256>>>();     // 2304 kkpairs x 1024 n / 256
    gemm_conv<1><<<dim3(8, 400), 512, GSMEM>>>(out);

    shift_h<<<(int)((HN + 255) / 256), 256>>>();
    im2col_kernel<2><<<4864 * 4, 256>>>();
    gemm_conv<2><<<dim3(8, 400), 512, GSMEM>>>(out);

    flat_kernel<<<NSAMP, 256>>>(out + O_EMB);
    head_kernel<<<NSAMP, 256>>>(cls_w, cls_b, reg_w, reg_b, out);
    decode_kernel<<<NSAMP, 32>>>(proposals);
    nms_kernel<<<2, 512>>>(out);
}

// round 13
// speedup vs baseline: 1.0620x; 1.0620x over previous
#include <cuda_runtime.h>
#include <cuda_fp16.h>
#include <math.h>
#include <stdint.h>

// ---------------- problem constants ----------------
#define NSAMP   1024
#define NCLS    9
#define PRE_K   512
#define DETS    100
#define IMGW    640.0f
#define IMGH    384.0f

#define O_EMB   ((size_t)0)
#define O_CLS   ((size_t)51380224)
#define O_REG   ((size_t)51389440)
#define O_BOX   ((size_t)51426304)
#define O_SCO   ((size_t)51427104)
#define O_LAB   ((size_t)51427304)
#define O_VAL   ((size_t)51427504)

// packed-M GEMM geometry: 1024 samples x 50 rows (49 valid + 1 pad), 400 m-tiles
#define MTILES 400
#define A_TILE_W 4352u          // words per A tile (64 rows x 68 words, 272B rows)

// ---------------- scratch (device globals; no allocation) ----------------
#define XN ((size_t)1024*512*56)
#define HN ((size_t)1024*1024*56)
__device__ __align__(16) __half g_x16r  [XN + 128];
__device__ __align__(16) __half g_x16lr [XN + 128];
__device__ __align__(16) __half g_x16sr [XN + 128];    // shifted by +1 half
__device__ __align__(16) __half g_x16lsr[XN + 128];
__device__ __align__(16) __half g_h16r  [HN + 128];
__device__ __align__(16) __half g_h16lr [HN + 128];
__device__ __align__(16) __half g_h16sr [HN + 128];
__device__ __align__(16) __half g_h16lsr[HN + 128];
#define X16   (g_x16r   + 64)
#define X16L  (g_x16lr  + 64)
#define X16S  (g_x16sr  + 64)
#define X16LS (g_x16lsr + 64)
#define H16   (g_h16r   + 64)
#define H16L  (g_h16lr  + 64)
#define H16S  (g_h16sr  + 64)
#define H16LS (g_h16lsr + 64)

// A^T im2col, tiled: tile (kc, mt) at ((kc*400+mt) * 4352) words; hi and lo
__device__ __align__(16) __half g_A1h[(size_t)72 *MTILES*2*A_TILE_W];
__device__ __align__(16) __half g_A1l[(size_t)72 *MTILES*2*A_TILE_W];
__device__ __align__(16) __half g_A2h[(size_t)152*MTILES*2*A_TILE_W];
__device__ __align__(16) __half g_A2l[(size_t)152*MTILES*2*A_TILE_W];

// B weights, tiled: tile (kc, nt) = 128 co x 72 halves (144B rows) = 18432 B
__device__ __align__(16) __half g_w1h[(size_t)72 *8*9216];
__device__ __align__(16) __half g_w1l[(size_t)72 *8*9216];
__device__ __align__(16) __half g_wbh[(size_t)152*8*9216];
__device__ __align__(16) __half g_wbl[(size_t)152*8*9216];

__device__ uint32_t g_mask[9][25];

__device__ float g_flat[(size_t)NSAMP*1024];
__device__ float g_cls[NSAMP*NCLS];
__device__ float g_reg[NSAMP*NCLS*4];
__device__ float g_boxes[NSAMP*NCLS*4];
__device__ float g_scores[NSAMP*NCLS];

// ================= PTX helpers =================
__device__ __forceinline__ uint32_t smem_u32(const void* p) {
    uint32_t a;
    asm("{ .reg .u64 t; cvta.to.shared.u64 t, %1; cvt.u32.u64 %0, t; }" : "=r"(a) : "l"(p));
    return a;
}
__device__ __forceinline__ void cp_bulk(uint32_t dst, const void* src, uint32_t bytes,
                                        uint32_t mbar) {
    asm volatile(
        "cp.async.bulk.shared::cluster.global.mbarrier::complete_tx::bytes [%0], [%1], %2, [%3];"
        :: "r"(dst), "l"(src), "r"(bytes), "r"(mbar) : "memory");
}
#define MBAR_INIT(mb, n) asm volatile("mbarrier.init.shared.b64 [%0], %1;" :: "r"(mb), "r"(n) : "memory")
#define MBAR_EXPECT(mb, tx) asm volatile("mbarrier.arrive.expect_tx.shared.b64 _, [%0], %1;" :: "r"(mb), "r"(tx) : "memory")
#define FENCE_ASYNC() asm volatile("fence.proxy.async.shared::cta;" ::: "memory")
__device__ __forceinline__ void mbar_wait(uint32_t mb, uint32_t parity) {
    asm volatile(
        "{\n\t.reg .pred P;\n\t"
        "W%=:\n\tmbarrier.try_wait.parity.acquire.cta.shared::cta.b64 P, [%0], %1, 0x989680;\n\t"
        "@!P bra W%=;\n\t}"
        :: "r"(mb), "r"(parity) : "memory");
}

__device__ __forceinline__ void ldm_x4(uint32_t* r, uint32_t a) {
    asm volatile("ldmatrix.sync.aligned.m8n8.x4.shared.b16 {%0,%1,%2,%3}, [%4];"
        : "=r"(r[0]), "=r"(r[1]), "=r"(r[2]), "=r"(r[3]) : "r"(a));
}
__device__ __forceinline__ void ldm_x4t(uint32_t* r, uint32_t a) {
    asm volatile("ldmatrix.sync.aligned.m8n8.x4.trans.shared.b16 {%0,%1,%2,%3}, [%4];"
        : "=r"(r[0]), "=r"(r[1]), "=r"(r[2]), "=r"(r[3]) : "r"(a));
}
// fp32-accumulator HMMA (main pass)
__device__ __forceinline__ void mma16816(float* c, const uint32_t* a, uint32_t b0, uint32_t b1) {
    asm volatile(
        "mma.sync.aligned.m16n8k16.row.col.f32.f16.f16.f32 "
        "{%0,%1,%2,%3}, {%4,%5,%6,%7}, {%8,%9}, {%0,%1,%2,%3};"
        : "+f"(c[0]), "+f"(c[1]), "+f"(c[2]), "+f"(c[3])
        : "r"(a[0]), "r"(a[1]), "r"(a[2]), "r"(a[3]), "r"(b0), "r"(b1));
}
// fp16-accumulator HMMA (correction passes; flushed to fp32 每 chunk)
__device__ __forceinline__ void mma16816h(uint32_t* c, const uint32_t* a, uint32_t b0, uint32_t b1) {
    asm volatile(
        "mma.sync.aligned.m16n8k16.row.col.f16.f16.f16.f16 "
        "{%0,%1}, {%2,%3,%4,%5}, {%6,%7}, {%0,%1};"
        : "+r"(c[0]), "+r"(c[1])
        : "r"(a[0]), "r"(a[1]), "r"(a[2]), "r"(a[3]), "r"(b0), "r"(b1));
}

// ---------------- conversion / prep kernels ----------------
// merged: hi/lo split + shifted copies in one pass
__global__ void cvt_x16(const float* __restrict__ x) {
    size_t i = (size_t)blockIdx.x * 256 + threadIdx.x;
    if (i >= XN) return;
    int p = (int)(i % 56);
    size_t row = i / 56;
    float v = (p < 49) ? x[row * 49 + p] : 0.f;
    __half hh = __float2half(v);
    __half hl = __float2half(v - __half2float(hh));
    X16[i]  = hh;
    X16L[i] = hl;
    X16S[i - 1]  = hh;     // S[j] = X[j+1]; i=0 lands in head guard
    X16LS[i - 1] = hl;
}
// weights -> tiled hi+lo [kc][co 128 x 72 halves]
__global__ void cvt_w1h(const float* __restrict__ w) {
    size_t i = (size_t)blockIdx.x * 256 + threadIdx.x;
    if (i >= (size_t)1024*4608) return;
    int co = (int)(i / 4608);
    int kk = (int)(i - (size_t)co * 4608);
    float v = w[i];
    __half hh = __float2half(v);
    size_t d = (size_t)((kk >> 6) * 8 + (co >> 7)) * 9216 + (co & 127) * 72 + (kk & 63);
    g_w1h[d] = hh;
    g_w1l[d] = __float2half(v - __half2float(hh));
}
__global__ void cvt_wbh(const float* __restrict__ w2, const float* __restrict__ wd) {
    size_t i = (size_t)blockIdx.x * 256 + threadIdx.x;
    if (i >= (size_t)1024*9728) return;
    int co = (int)(i / 9728);
    int kk = (int)(i - (size_t)co * 9728);
    float v = (kk < 9216) ? w2[(size_t)co * 9216 + kk] : wd[(size_t)co * 512 + (kk - 9216)];
    __half hh = __float2half(v);
    size_t d = (size_t)((kk >> 6) * 8 + (co >> 7)) * 9216 + (co & 127) * 72 + (kk & 63);
    g_wbh[d] = hh;
    g_wbl[d] = __float2half(v - __half2float(hh));
}
__global__ void init_mask() {
    int t = threadIdx.x;
    if (t >= 225) return;
    int off = t / 25, w = t - (t / 25) * 25;
    int ky = off / 3, kx = off - (off / 3) * 3;
    uint32_t m = 0;
    #pragma unroll
    for (int h = 0; h < 2; h++) {
        int p = 2 * w + h;
        if (p < 49) {
            int y = p / 7, x = p - (p / 7) * 7;
            int yy = y + ky - 1, xx = x + kx - 1;
            if (yy >= 0 && yy < 7 && xx >= 0 && xx < 7) m |= 0xFFFFu << (16 * h);
        }
    }
    g_mask[off][w] = m;
}

// ---------------- im2col to tiled global A^T (hi + lo) ----------------
template<int P>
__global__ void im2col_kernel() {
    int idx = blockIdx.x * 256 + threadIdx.x;
    int n  = idx & 1023;
    int kk = idx >> 10;
    const int KK = (P == 1) ? 4608 : 9728;
    if (kk >= KK) return;

    int ci, off;
    const __half *H, *Hs, *L, *Ls;
    int CI;
    if (P == 2 && kk >= 9216) {
        ci = kk - 9216; off = 4;                 // center tap, del = 0
        H = X16; Hs = X16S; L = X16L; Ls = X16LS; CI = 512;
    } else {
        ci = kk / 9; off = kk - ci * 9;
        if (P == 1) { H = X16; Hs = X16S; L = X16L; Ls = X16LS; CI = 512; }
        else        { H = H16; Hs = H16S; L = H16L; Ls = H16LS; CI = 1024; }
    }
    int ky = off / 3, kx = off - ky * 3;
    int del = (ky - 1) * 7 + (kx - 1);
    int sh  = del & 1;
    int ws  = (del - sh) >> 1;

    const uint32_t* src  = (const uint32_t*)((sh ? Hs : H) + (size_t)(n * CI + ci) * 56) + ws;
    const uint32_t* srcL = (const uint32_t*)((sh ? Ls : L) + (size_t)(n * CI + ci) * 56) + ws;
    uint32_t* dh_b = (uint32_t*)((P == 1) ? g_A1h : g_A2h);
    uint32_t* dl_b = (uint32_t*)((P == 1) ? g_A1l : g_A2l);
    const uint32_t* mk = g_mask[off];

    size_t base = (size_t)(kk >> 6) * MTILES * A_TILE_W + (size_t)(kk & 63) * 68;
    int m0 = n * 50;
    #pragma unroll
    for (int w = 0; w < 25; w++) {
        int m = m0 + 2 * w;
        size_t d = base + (size_t)(m >> 7) * A_TILE_W + ((m & 127) >> 1);
        uint32_t mm = mk[w];
        dh_b[d] = src[w]  & mm;
        dl_b[d] = srcL[w] & mm;
    }
}

// ---------------- split GEMM: fp32-acc main + fp16-acc corrections, TMA-fed ----------------
// smem per stage: Ah 17408, Al 17408, Bh 18432, Bl 18432
#define AHO(st) ((uint32_t)(st) * 17408u)
#define ALO(st) (52224u + (uint32_t)(st) * 17408u)
#define BHO(st) (104448u + (uint32_t)(st) * 18432u)
#define BLO(st) (159744u + (uint32_t)(st) * 18432u)
#define MB_OFF  215040u
#define GSMEM   215072
#define CHUNK_TX 71680u

__device__ __forceinline__ void mma8f(float (*acc)[4], const uint32_t A[2][4],
                                      const uint32_t Q0[4], const uint32_t Q1[4]) {
    #pragma unroll
    for (int i = 0; i < 2; i++) {
        mma16816(acc[i*4+0], A[i], Q0[0], Q0[2]);
        mma16816(acc[i*4+1], A[i], Q0[1], Q0[3]);
        mma16816(acc[i*4+2], A[i], Q1[0], Q1[2]);
        mma16816(acc[i*4+3], A[i], Q1[1], Q1[3]);
    }
}
__device__ __forceinline__ void mma8h(uint32_t (*q)[2], const uint32_t A[2][4],
                                      const uint32_t Q0[4], const uint32_t Q1[4]) {
    #pragma unroll
    for (int i = 0; i < 2; i++) {
        mma16816h(q[i*4+0], A[i], Q0[0], Q0[2]);
        mma16816h(q[i*4+1], A[i], Q0[1], Q0[3]);
        mma16816h(q[i*4+2], A[i], Q1[0], Q1[2]);
        mma16816h(q[i*4+3], A[i], Q1[1], Q1[3]);
    }
}

template<int P>
__global__ void __launch_bounds__(512, 1) gemm_conv(float* __restrict__ d_out) {
    extern __shared__ char smem[];
    const uint32_t sb = smem_u32(smem);
    const int tid  = threadIdx.x;
    const int lane = tid & 31;
    const int wid  = tid >> 5;                 // 16 warps
    const int wm   = wid >> 2, wn = wid & 3;   // 4x4 warp grid, 32x32 tiles
    const int nt   = blockIdx.x;               // 8 n-tiles
    const int mt   = blockIdx.y;               // 400 m-tiles

    const char* Ah_g = (const char*)((P == 1) ? g_A1h : g_A2h);
    const char* Al_g = (const char*)((P == 1) ? g_A1l : g_A2l);
    const char* Bh_g = (const char*)((P == 1) ? g_w1h : g_wbh);
    const char* Bl_g = (const char*)((P == 1) ? g_w1l : g_wbl);
    const int NC = (P == 1) ? 72 : 152;

    if (tid == 0) {
        MBAR_INIT(sb + MB_OFF + 0, 1);
        MBAR_INIT(sb + MB_OFF + 8, 1);
        MBAR_INIT(sb + MB_OFF + 16, 1);
        FENCE_ASYNC();
    }
    __syncthreads();

    auto issue = [&](int c) {
        if (c < NC && tid == 0) {
            int st = c - (c / 3) * 3;
            uint32_t mb = sb + MB_OFF + (uint32_t)st * 8u;
            MBAR_EXPECT(mb, CHUNK_TX);
            cp_bulk(sb + AHO(st), Ah_g + ((size_t)c * MTILES + mt) * 17408, 17408u, mb);
            cp_bulk(sb + ALO(st), Al_g + ((size_t)c * MTILES + mt) * 17408, 17408u, mb);
            cp_bulk(sb + BHO(st), Bh_g + ((size_t)c * 8 + nt) * 18432, 18432u, mb);
            cp_bulk(sb + BLO(st), Bl_g + ((size_t)c * 8 + nt) * 18432, 18432u, mb);
        }
    };

    float acc[8][4];
    #pragma unroll
    for (int i = 0; i < 8; i++)
        #pragma unroll
        for (int e = 0; e < 4; e++) acc[i][e] = 0.f;

    const uint32_t aRow = ((lane & 7) + ((lane >> 4) & 1) * 8) * 272u
                        + (uint32_t)(wm * 32 + ((lane >> 3) & 1) * 8) * 2u;
    const uint32_t bRow = (uint32_t)(wn * 32 + (lane & 15)) * 144u + ((lane >> 4) & 1) * 16u;

    issue(0); issue(1);

    for (int c = 0; c < NC; c++) {
        int st = c - (c / 3) * 3;
        mbar_wait(sb + MB_OFF + (uint32_t)st * 8u, (uint32_t)((c / 3) & 1));
        __syncthreads();                       // stage (c-1)%3 fully consumed
        issue(c + 2);                          // refill stage (c+2)%3 == (c-1)%3
        const uint32_t Ahs = sb + AHO(st), Als = sb + ALO(st);
        const uint32_t Bhs = sb + BHO(st), Bls = sb + BLO(st);

        uint32_t qacc[8][2];                   // fp16x2 correction accumulators
        #pragma unroll
        for (int i = 0; i < 8; i++) { qacc[i][0] = 0u; qacc[i][1] = 0u; }

        #pragma unroll
        for (int ks = 0; ks < 4; ks++) {
            uint32_t A[2][4], AL[2][4], Q0[4], Q1[4], R0[4], R1[4];
            const uint32_t ao = aRow + (uint32_t)ks * (16u * 272u);
            const uint32_t bo = bRow + (uint32_t)ks * 32u;
            ldm_x4t(A[0],  Ahs + ao);
            ldm_x4t(A[1],  Ahs + ao + 32u);
            ldm_x4t(AL[0], Als + ao);
            ldm_x4t(AL[1], Als + ao + 32u);
            ldm_x4(Q0, Bhs + bo);
            ldm_x4(Q1, Bhs + bo + 16u * 144u);
            ldm_x4(R0, Bls + bo);
            ldm_x4(R1, Bls + bo + 16u * 144u);
            mma8f(&acc[0],  A,  Q0, Q1);       // Ah*Bh  (fp32 acc)
            mma8h(&qacc[0], AL, Q0, Q1);       // Al*Bh  (fp16 acc)
            mma8h(&qacc[0], A,  R0, R1);       // Ah*Bl  (fp16 acc)
        }
        // flush fp16 correction accumulators into fp32 (caps f16 accumulation at K=64)
        #pragma unroll
        for (int i = 0; i < 8; i++) {
            float2 lo = __half22float2(*(__half2*)&qacc[i][0]);
            float2 hi = __half22float2(*(__half2*)&qacc[i][1]);
            acc[i][0] += lo.x; acc[i][1] += lo.y;
            acc[i][2] += hi.x; acc[i][3] += hi.y;
        }
    }
    __syncthreads();

    // ---- epilogue: relu, stage through smem [128 co][132 m] ----
    float* sf = (float*)smem;
    #pragma unroll
    for (int i = 0; i < 2; i++) {
        #pragma unroll
        for (int j = 0; j < 4; j++) {
            int m  = wm * 32 + i * 16 + (lane >> 2);
            int co = wn * 32 + j * 8 + ((lane & 3) << 1);
            const float* a = acc[i*4+j];
            sf[co * 132 + m]           = fmaxf(a[0], 0.f);
            sf[(co + 1) * 132 + m]     = fmaxf(a[1], 0.f);
            sf[co * 132 + m + 8]       = fmaxf(a[2], 0.f);
            sf[(co + 1) * 132 + m + 8] = fmaxf(a[3], 0.f);
        }
    }
    __syncthreads();
    for (int idx = tid; idx < 128 * 128; idx += 512) {
        int co_l = idx >> 7, ml = idx & 127;
        int m_g = mt * 128 + ml;
        int n = m_g / 50;
        int p = m_g - n * 50;
        if (p < 49) {
            float v = sf[co_l * 132 + ml];
            int co_g = nt * 128 + co_l;
            if (P == 1) {
                size_t o = ((size_t)(n * 1024 + co_g)) * 56 + p;
                __half hh = __float2half(v);
                __half hl = __float2half(v - __half2float(hh));
                H16[o]  = hh;
                H16L[o] = hl;
                H16S[o - 1]  = hh;     // fused shift_h: S[j] = H[j+1]
                H16LS[o - 1] = hl;
            } else {
                d_out[O_EMB + ((size_t)(n * 1024 + co_g)) * 49 + p] = v;
            }
        }
    }
}

// ---------------- avg pool ----------------
__global__ void flat_kernel(const float* __restrict__ emb) {
    int n = blockIdx.x;
    for (int co = threadIdx.x; co < 1024; co += 256) {
        const float* e = emb + ((size_t)n * 1024 + co) * 49;
        float s = 0.f;
        #pragma unroll
        for (int p = 0; p < 49; p++) s += e[p];
        g_flat[(size_t)n * 1024 + co] = s / 49.0f;
    }
}

// ---------------- head GEMMs ----------------
__global__ void head_kernel(const float* __restrict__ cls_w, const float* __restrict__ cls_b,
                            const float* __restrict__ reg_w, const float* __restrict__ reg_b,
                            float* __restrict__ d_out) {
    int n = blockIdx.x;
    int w = threadIdx.x >> 5, lane = threadIdx.x & 31;
    const float* f = g_flat + (size_t)n * 1024;
    for (int o = w; o < 45; o += 8) {
        const float* wr; float bias;
        if (o < NCLS) { wr = cls_w + (size_t)o * 1024; bias = cls_b[o]; }
        else          { wr = reg_w + (size_t)(o - NCLS) * 1024; bias = reg_b[o - NCLS]; }
        float acc = 0.f;
        for (int k = lane; k < 1024; k += 32) acc += f[k] * wr[k];
        #pragma unroll
        for (int d = 16; d; d >>= 1) acc += __shfl_xor_sync(0xffffffffu, acc, d);
        if (lane == 0) {
            float v = acc + bias;
            if (o < NCLS) { g_cls[n * NCLS + o] = v; d_out[O_CLS + n * NCLS + o] = v; }
            else { g_reg[n * 36 + (o - NCLS)] = v; d_out[O_REG + n * 36 + (o - NCLS)] = v; }
        }
    }
}

// ---------------- softmax + box decode + clip ----------------
__global__ void decode_kernel(const float* __restrict__ proposals) {
    int n = blockIdx.x; int lane = threadIdx.x;
    float logit = (lane < NCLS) ? g_cls[n * NCLS + lane] : -INFINITY;
    float m = logit;
    #pragma unroll
    for (int d = 16; d; d >>= 1) m = fmaxf(m, __shfl_xor_sync(0xffffffffu, m, d));
    float e = (lane < NCLS) ? expf(logit - m) : 0.f;
    float s = e;
    #pragma unroll
    for (int d = 16; d; d >>= 1) s += __shfl_xor_sync(0xffffffffu, s, d);
    if (lane < NCLS) {
        g_scores[n * NCLS + lane] = e / s;
        const float* pr = proposals + (size_t)n * 4;
        float pw = pr[2] - pr[0], ph = pr[3] - pr[1];
        float pcx = pr[0] + 0.5f * pw, pcy = pr[1] + 0.5f * ph;
        const float* rr = g_reg + n * 36 + lane * 4;
        float dx = rr[0] / 10.0f, dy = rr[1] / 10.0f;
        float dw = fminf(rr[2] / 5.0f, 4.135166556742356f);
        float dh = fminf(rr[3] / 5.0f, 4.135166556742356f);
        float ncx = dx * pw + pcx, ncy = dy * ph + pcy;
        float nw = expf(dw) * pw, nh = expf(dh) * ph;
        float b0 = fminf(fmaxf(ncx - 0.5f * nw, 0.f), IMGW);
        float b1 = fminf(fmaxf(ncy - 0.5f * nh, 0.f), IMGH);
        float b2 = fminf(fmaxf(ncx + 0.5f * nw, 0.f), IMGW);
        float b3 = fminf(fmaxf(ncy + 0.5f * nh, 0.f), IMGH);
        float* bp = g_boxes + (size_t)(n * NCLS + lane) * 4;
        bp[0] = b0; bp[1] = b1; bp[2] = b2; bp[3] = b3;
    }
}

// ---------------- per-image: filter -> sort(4096) -> NMS(512) -> top-100 ----------------
__global__ void __launch_bounds__(512) nms_kernel(float* __restrict__ d_out) {
    __shared__ float skey[4096];
    __shared__ int   sidx[4096];
    __shared__ float sbox[PRE_K * 4];
    __shared__ int   skeep[PRE_K];
    __shared__ int   swsum[16];

    int img = blockIdx.x; int tid = threadIdx.x;

    for (int j = tid; j < 4096; j += 512) {
        int p = j >> 3, c = (j & 7) + 1;
        int n = img * 512 + p;
        float s = g_scores[n * NCLS + c];
        const float* bb = g_boxes + (size_t)(n * NCLS + c) * 4;
        bool valid = (s > 0.05f) && ((bb[2] - bb[0]) >= 0.01f) && ((bb[3] - bb[1]) >= 0.01f);
        skey[j] = valid ? s : -INFINITY;
        sidx[j] = j;
    }
    __syncthreads();

    for (int k = 2; k <= 4096; k <<= 1) {
        for (int j2 = k >> 1; j2 > 0; j2 >>= 1) {
            for (int i = tid; i < 4096; i += 512) {
                int ixj = i ^ j2;
                if (ixj > i) {
                    float ka = skey[i], kb = skey[ixj];
                    int ia = sidx[i], ib = sidx[ixj];
                    bool a_first = (ka > kb) || (ka == kb && ia < ib);
                    bool up = ((i & k) == 0);
                    if (up ? !a_first : a_first) {
                        skey[i] = kb; skey[ixj] = ka;
                        sidx[i] = ib; sidx[ixj] = ia;
                    }
                }
            }
            __syncthreads();
        }
    }

    if (tid < PRE_K) {
        float s = skey[tid];
        int j = sidx[tid];
        int p = j >> 3, c = (j & 7) + 1;
        int n = img * 512 + p;
        const float* bb = g_boxes + (size_t)(n * NCLS + c) * 4;
        float off = 641.0f * (float)c;
        sbox[tid * 4 + 0] = bb[0] + off;
        sbox[tid * 4 + 1] = bb[1] + off;
        sbox[tid * 4 + 2] = bb[2] + off;
        sbox[tid * 4 + 3] = bb[3] + off;
        skeep[tid] = (s != -INFINITY) ? 1 : 0;
    }
    __syncthreads();

    for (int i = 0; i < PRE_K; i++) {
        if (skeep[i]) {
            int j = tid;
            if (j > i && skeep[j]) {
                float ax0 = sbox[i*4], ay0 = sbox[i*4+1], ax1 = sbox[i*4+2], ay1 = sbox[i*4+3];
                float bx0 = sbox[j*4], by0 = sbox[j*4+1], bx1 = sbox[j*4+2], by1 = sbox[j*4+3];
                float areaA = (ax1 - ax0) * (ay1 - ay0);
                float areaB = (bx1 - bx0) * (by1 - by0);
                float iw = fmaxf(fminf(ax1, bx1) - fmaxf(ax0, bx0), 0.f);
                float ih = fmaxf(fminf(ay1, by1) - fmaxf(ay0, by0), 0.f);
                float inter = iw * ih;
                float iou = inter / fmaxf(areaA + areaB - inter, 1e-8f);
                if (iou > 0.5f) skeep[j] = 0;
            }
        }
        __syncthreads();
    }

    int keepflag = (tid < PRE_K) ? skeep[tid] : 0;
    unsigned mask = __ballot_sync(0xffffffffu, keepflag != 0);
    int lane = tid & 31, wid = tid >> 5;
    if (lane == 0) swsum[wid] = __popc(mask);
    __syncthreads();
    int base = 0;
    for (int w = 0; w < wid; w++) base += swsum[w];
    int rank = base + __popc(mask & ((1u << lane) - 1u));

    float* dbx = d_out + O_BOX + (size_t)img * DETS * 4;
    float* dsc = d_out + O_SCO + (size_t)img * DETS;
    float* dlb = d_out + O_LAB + (size_t)img * DETS;
    float* dvl = d_out + O_VAL + (size_t)img * DETS;
    for (int i = tid; i < DETS; i += 512) {
        dbx[i*4+0] = 0.f; dbx[i*4+1] = 0.f; dbx[i*4+2] = 0.f; dbx[i*4+3] = 0.f;
        dsc[i] = 0.f; dlb[i] = 0.f; dvl[i] = 0.f;
    }
    __syncthreads();
    if (keepflag && rank < DETS) {
        int j = sidx[tid];
        int p = j >> 3, c = (j & 7) + 1;
        int n = img * 512 + p;
        const float* bb = g_boxes + (size_t)(n * NCLS + c) * 4;
        dbx[rank*4+0] = bb[0]; dbx[rank*4+1] = bb[1];
        dbx[rank*4+2] = bb[2]; dbx[rank*4+3] = bb[3];
        dsc[rank] = skey[tid];
        dlb[rank] = (float)c;
        dvl[rank] = 1.0f;
    }
}

// ---------------- launch ----------------
extern "C" void kernel_launch(void* const* d_in, const int* in_sizes, int n_in,
                              void* d_out, int out_size) {
    const float* feats     = (const float*)d_in[0];
    const float* proposals = (const float*)d_in[1];
    const float* w1        = (const float*)d_in[2];
    const float* w2        = (const float*)d_in[3];
    const float* wd        = (const float*)d_in[4];
    const float* cls_w     = (const float*)d_in[5];
    const float* cls_b     = (const float*)d_in[6];
    const float* reg_w     = (const float*)d_in[7];
    const float* reg_b     = (const float*)d_in[8];
    float* out = (float*)d_out;

    cudaFuncSetAttribute(gemm_conv<1>, cudaFuncAttributeMaxDynamicSharedMemorySize, GSMEM);
    cudaFuncSetAttribute(gemm_conv<2>, cudaFuncAttributeMaxDynamicSharedMemorySize, GSMEM);

    cvt_x16<<<(int)((XN + 255) / 256), 256>>>(feats);
    cvt_w1h<<<(int)(((size_t)1024*4608 + 255) / 256), 256>>>(w1);
    cvt_wbh<<<(int)(((size_t)1024*9728 + 255) / 256), 256>>>(w2, wd);
    init_mask<<<1, 256>>>();

    im2col_kernel<1><<<4608 * 4, 256>>>();
    gemm_conv<1><<<dim3(8, 400), 512, GSMEM>>>(out);

    im2col_kernel<2><<<9728 * 4, 256>>>();
    gemm_conv<2><<<dim3(8, 400), 512, GSMEM>>>(out);

    flat_kernel<<<NSAMP, 256>>>(out + O_EMB);
    head_kernel<<<NSAMP, 256>>>(cls_w, cls_b, reg_w, reg_b, out);
    decode_kernel<<<NSAMP, 32>>>(proposals);
    nms_kernel<<<2, 512>>>(out);
}

// round 14
// speedup vs baseline: 1.0629x; 1.0009x over previous
#include <cuda_runtime.h>
#include <cuda_fp16.h>
#include <math.h>
#include <stdint.h>

// ---------------- problem constants ----------------
#define NSAMP   1024
#define NCLS    9
#define PRE_K   512
#define DETS    100
#define IMGW    640.0f
#define IMGH    384.0f

#define O_EMB   ((size_t)0)
#define O_CLS   ((size_t)51380224)
#define O_REG   ((size_t)51389440)
#define O_BOX   ((size_t)51426304)
#define O_SCO   ((size_t)51427104)
#define O_LAB   ((size_t)51427304)
#define O_VAL   ((size_t)51427504)

// packed-M GEMM geometry: 1024 samples x 50 rows (49 valid + 1 pad), 400 m-tiles
#define MTILES 400
#define A_TILE_W 4352u          // words per A tile (64 rows x 68 words, 272B rows)

// ---------------- scratch (device globals; no allocation) ----------------
#define XN ((size_t)1024*512*56)
#define HN ((size_t)1024*1024*56)
__device__ __align__(16) __half g_x16r [XN + 128];
__device__ __align__(16) __half g_x16lr[XN + 128];
__device__ __align__(16) __half g_h16r [HN + 128];
__device__ __align__(16) __half g_h16lr[HN + 128];
#define X16  (g_x16r  + 64)
#define X16L (g_x16lr + 64)
#define H16  (g_h16r  + 64)
#define H16L (g_h16lr + 64)

// A^T im2col, tiled: tile (kc, mt) at ((kc*400+mt) * 4352) words; hi and lo
__device__ __align__(16) __half g_A1h[(size_t)72 *MTILES*2*A_TILE_W];
__device__ __align__(16) __half g_A1l[(size_t)72 *MTILES*2*A_TILE_W];
__device__ __align__(16) __half g_A2h[(size_t)152*MTILES*2*A_TILE_W];
__device__ __align__(16) __half g_A2l[(size_t)152*MTILES*2*A_TILE_W];

// B weights, tiled: tile (kc, nt) = 128 co x 72 halves (144B rows) = 18432 B
__device__ __align__(16) __half g_w1h[(size_t)72 *8*9216];
__device__ __align__(16) __half g_w1l[(size_t)72 *8*9216];
__device__ __align__(16) __half g_wbh[(size_t)152*8*9216];
__device__ __align__(16) __half g_wbl[(size_t)152*8*9216];

__device__ uint32_t g_mask[9][25];

__device__ float g_flat[(size_t)NSAMP*1024];
__device__ float g_cls[NSAMP*NCLS];
__device__ float g_reg[NSAMP*NCLS*4];
__device__ float g_boxes[NSAMP*NCLS*4];
__device__ float g_scores[NSAMP*NCLS];

// ================= PTX helpers =================
__device__ __forceinline__ uint32_t smem_u32(const void* p) {
    uint32_t a;
    asm("{ .reg .u64 t; cvta.to.shared.u64 t, %1; cvt.u32.u64 %0, t; }" : "=r"(a) : "l"(p));
    return a;
}
__device__ __forceinline__ void cp_bulk(uint32_t dst, const void* src, uint32_t bytes,
                                        uint32_t mbar) {
    asm volatile(
        "cp.async.bulk.shared::cluster.global.mbarrier::complete_tx::bytes [%0], [%1], %2, [%3];"
        :: "r"(dst), "l"(src), "r"(bytes), "r"(mbar) : "memory");
}
#define MBAR_INIT(mb, n) asm volatile("mbarrier.init.shared.b64 [%0], %1;" :: "r"(mb), "r"(n) : "memory")
#define MBAR_EXPECT(mb, tx) asm volatile("mbarrier.arrive.expect_tx.shared.b64 _, [%0], %1;" :: "r"(mb), "r"(tx) : "memory")
#define FENCE_ASYNC() asm volatile("fence.proxy.async.shared::cta;" ::: "memory")
__device__ __forceinline__ void mbar_wait(uint32_t mb, uint32_t parity) {
    asm volatile(
        "{\n\t.reg .pred P;\n\t"
        "W%=:\n\tmbarrier.try_wait.parity.acquire.cta.shared::cta.b64 P, [%0], %1, 0x989680;\n\t"
        "@!P bra W%=;\n\t}"
        :: "r"(mb), "r"(parity) : "memory");
}

__device__ __forceinline__ void ldm_x4(uint32_t* r, uint32_t a) {
    asm volatile("ldmatrix.sync.aligned.m8n8.x4.shared.b16 {%0,%1,%2,%3}, [%4];"
        : "=r"(r[0]), "=r"(r[1]), "=r"(r[2]), "=r"(r[3]) : "r"(a));
}
__device__ __forceinline__ void ldm_x4t(uint32_t* r, uint32_t a) {
    asm volatile("ldmatrix.sync.aligned.m8n8.x4.trans.shared.b16 {%0,%1,%2,%3}, [%4];"
        : "=r"(r[0]), "=r"(r[1]), "=r"(r[2]), "=r"(r[3]) : "r"(a));
}
// fp32-accumulator HMMA (main pass)
__device__ __forceinline__ void mma16816(float* c, const uint32_t* a, uint32_t b0, uint32_t b1) {
    asm volatile(
        "mma.sync.aligned.m16n8k16.row.col.f32.f16.f16.f32 "
        "{%0,%1,%2,%3}, {%4,%5,%6,%7}, {%8,%9}, {%0,%1,%2,%3};"
        : "+f"(c[0]), "+f"(c[1]), "+f"(c[2]), "+f"(c[3])
        : "r"(a[0]), "r"(a[1]), "r"(a[2]), "r"(a[3]), "r"(b0), "r"(b1));
}
// fp16-accumulator HMMA (correction passes; flushed to fp32 per chunk)
__device__ __forceinline__ void mma16816h(uint32_t* c, const uint32_t* a, uint32_t b0, uint32_t b1) {
    asm volatile(
        "mma.sync.aligned.m16n8k16.row.col.f16.f16.f16.f16 "
        "{%0,%1}, {%2,%3,%4,%5}, {%6,%7}, {%0,%1};"
        : "+r"(c[0]), "+r"(c[1])
        : "r"(a[0]), "r"(a[1]), "r"(a[2]), "r"(a[3]), "r"(b0), "r"(b1));
}

// ---------------- conversion / prep kernels ----------------
__global__ void cvt_x16(const float* __restrict__ x) {
    size_t i = (size_t)blockIdx.x * 256 + threadIdx.x;
    if (i >= XN) return;
    int p = (int)(i % 56);
    size_t row = i / 56;
    float v = (p < 49) ? x[row * 49 + p] : 0.f;
    __half hh = __float2half(v);
    X16[i]  = hh;
    X16L[i] = __float2half(v - __half2float(hh));
}
// weights -> tiled hi+lo [kc][co 128 x 72 halves]
__global__ void cvt_w1h(const float* __restrict__ w) {
    size_t i = (size_t)blockIdx.x * 256 + threadIdx.x;
    if (i >= (size_t)1024*4608) return;
    int co = (int)(i / 4608);
    int kk = (int)(i - (size_t)co * 4608);
    float v = w[i];
    __half hh = __float2half(v);
    size_t d = (size_t)((kk >> 6) * 8 + (co >> 7)) * 9216 + (co & 127) * 72 + (kk & 63);
    g_w1h[d] = hh;
    g_w1l[d] = __float2half(v - __half2float(hh));
}
__global__ void cvt_wbh(const float* __restrict__ w2, const float* __restrict__ wd) {
    size_t i = (size_t)blockIdx.x * 256 + threadIdx.x;
    if (i >= (size_t)1024*9728) return;
    int co = (int)(i / 9728);
    int kk = (int)(i - (size_t)co * 9728);
    float v = (kk < 9216) ? w2[(size_t)co * 9216 + kk] : wd[(size_t)co * 512 + (kk - 9216)];
    __half hh = __float2half(v);
    size_t d = (size_t)((kk >> 6) * 8 + (co >> 7)) * 9216 + (co & 127) * 72 + (kk & 63);
    g_wbh[d] = hh;
    g_wbl[d] = __float2half(v - __half2float(hh));
}
__global__ void init_mask() {
    int t = threadIdx.x;
    if (t >= 225) return;
    int off = t / 25, w = t - (t / 25) * 25;
    int ky = off / 3, kx = off - (off / 3) * 3;
    uint32_t m = 0;
    #pragma unroll
    for (int h = 0; h < 2; h++) {
        int p = 2 * w + h;
        if (p < 49) {
            int y = p / 7, x = p - (p / 7) * 7;
            int yy = y + ky - 1, xx = x + kx - 1;
            if (yy >= 0 && yy < 7 && xx >= 0 && xx < 7) m |= 0xFFFFu << (16 * h);
        }
    }
    g_mask[off][w] = m;
}

// ---------------- im2col to tiled global A^T (hi + lo), funnelshift for odd taps ----------------
template<int P>
__global__ void im2col_kernel() {
    int idx = blockIdx.x * 256 + threadIdx.x;
    int n  = idx & 1023;
    int kk = idx >> 10;
    const int KK = (P == 1) ? 4608 : 9728;
    if (kk >= KK) return;

    int ci, off;
    const __half *H, *L;
    int CI;
    if (P == 2 && kk >= 9216) {
        ci = kk - 9216; off = 4;                 // center tap, del = 0
        H = X16; L = X16L; CI = 512;
    } else {
        ci = kk / 9; off = kk - ci * 9;
        if (P == 1) { H = X16; L = X16L; CI = 512; }
        else        { H = H16; L = H16L; CI = 1024; }
    }
    int ky = off / 3, kx = off - ky * 3;
    int del = (ky - 1) * 7 + (kx - 1);
    long i0 = (long)(n * CI + ci) * 56 + del;    // image half-index of local m=0

    uint32_t* dh_b = (uint32_t*)((P == 1) ? g_A1h : g_A2h);
    uint32_t* dl_b = (uint32_t*)((P == 1) ? g_A1l : g_A2l);
    const uint32_t* mk = g_mask[off];
    size_t base = (size_t)(kk >> 6) * MTILES * A_TILE_W + (size_t)(kk & 63) * 68;
    int m0 = n * 50;

    if ((i0 & 1) == 0) {
        const uint32_t* sh = (const uint32_t*)H + (i0 >> 1);
        const uint32_t* sl = (const uint32_t*)L + (i0 >> 1);
        #pragma unroll
        for (int w = 0; w < 25; w++) {
            int m = m0 + 2 * w;
            size_t d = base + (size_t)(m >> 7) * A_TILE_W + ((m & 127) >> 1);
            uint32_t mm = mk[w];
            dh_b[d] = sh[w] & mm;
            dl_b[d] = sl[w] & mm;
        }
    } else {
        // words hold halves X[i0-1+2w], X[i0+2w]; pair(m=2w) = (u[w].hi, u[w+1].lo)
        const uint32_t* sh = (const uint32_t*)H + ((i0 - 1) >> 1);
        const uint32_t* sl = (const uint32_t*)L + ((i0 - 1) >> 1);
        #pragma unroll
        for (int w = 0; w < 25; w++) {
            int m = m0 + 2 * w;
            size_t d = base + (size_t)(m >> 7) * A_TILE_W + ((m & 127) >> 1);
            uint32_t mm = mk[w];
            dh_b[d] = __funnelshift_r(sh[w], sh[w + 1], 16) & mm;
            dl_b[d] = __funnelshift_r(sl[w], sl[w + 1], 16) & mm;
        }
    }
}

// ---------------- split GEMM: fp32-acc main + fp16-acc corrections, TMA-fed ----------------
// smem per stage: Ah 17408, Al 17408, Bh 18432, Bl 18432
#define AHO(st) ((uint32_t)(st) * 17408u)
#define ALO(st) (52224u + (uint32_t)(st) * 17408u)
#define BHO(st) (104448u + (uint32_t)(st) * 18432u)
#define BLO(st) (159744u + (uint32_t)(st) * 18432u)
#define MB_OFF  215040u
#define GSMEM   215072
#define CHUNK_TX 71680u

__device__ __forceinline__ void mma8f(float (*acc)[4], const uint32_t A[2][4],
                                      const uint32_t Q0[4], const uint32_t Q1[4]) {
    #pragma unroll
    for (int i = 0; i < 2; i++) {
        mma16816(acc[i*4+0], A[i], Q0[0], Q0[2]);
        mma16816(acc[i*4+1], A[i], Q0[1], Q0[3]);
        mma16816(acc[i*4+2], A[i], Q1[0], Q1[2]);
        mma16816(acc[i*4+3], A[i], Q1[1], Q1[3]);
    }
}
__device__ __forceinline__ void mma8h(uint32_t (*q)[2], const uint32_t A[2][4],
                                      const uint32_t Q0[4], const uint32_t Q1[4]) {
    #pragma unroll
    for (int i = 0; i < 2; i++) {
        mma16816h(q[i*4+0], A[i], Q0[0], Q0[2]);
        mma16816h(q[i*4+1], A[i], Q0[1], Q0[3]);
        mma16816h(q[i*4+2], A[i], Q1[0], Q1[2]);
        mma16816h(q[i*4+3], A[i], Q1[1], Q1[3]);
    }
}

template<int P>
__global__ void __launch_bounds__(512, 1) gemm_conv(float* __restrict__ d_out) {
    extern __shared__ char smem[];
    const uint32_t sb = smem_u32(smem);
    const int tid  = threadIdx.x;
    const int lane = tid & 31;
    const int wid  = tid >> 5;                 // 16 warps
    const int wm   = wid >> 2, wn = wid & 3;   // 4x4 warp grid, 32x32 tiles
    const int nt   = blockIdx.x;               // 8 n-tiles
    const int mt   = blockIdx.y;               // 400 m-tiles

    const char* Ah_g = (const char*)((P == 1) ? g_A1h : g_A2h);
    const char* Al_g = (const char*)((P == 1) ? g_A1l : g_A2l);
    const char* Bh_g = (const char*)((P == 1) ? g_w1h : g_wbh);
    const char* Bl_g = (const char*)((P == 1) ? g_w1l : g_wbl);
    const int NC = (P == 1) ? 72 : 152;

    if (tid == 0) {
        MBAR_INIT(sb + MB_OFF + 0, 1);
        MBAR_INIT(sb + MB_OFF + 8, 1);
        MBAR_INIT(sb + MB_OFF + 16, 1);
        FENCE_ASYNC();
    }
    __syncthreads();

    auto issue = [&](int c) {
        if (c < NC && tid == 0) {
            int st = c - (c / 3) * 3;
            uint32_t mb = sb + MB_OFF + (uint32_t)st * 8u;
            MBAR_EXPECT(mb, CHUNK_TX);
            cp_bulk(sb + AHO(st), Ah_g + ((size_t)c * MTILES + mt) * 17408, 17408u, mb);
            cp_bulk(sb + ALO(st), Al_g + ((size_t)c * MTILES + mt) * 17408, 17408u, mb);
            cp_bulk(sb + BHO(st), Bh_g + ((size_t)c * 8 + nt) * 18432, 18432u, mb);
            cp_bulk(sb + BLO(st), Bl_g + ((size_t)c * 8 + nt) * 18432, 18432u, mb);
        }
    };

    float acc[8][4];
    #pragma unroll
    for (int i = 0; i < 8; i++)
        #pragma unroll
        for (int e = 0; e < 4; e++) acc[i][e] = 0.f;

    const uint32_t aRow = ((lane & 7) + ((lane >> 4) & 1) * 8) * 272u
                        + (uint32_t)(wm * 32 + ((lane >> 3) & 1) * 8) * 2u;
    const uint32_t bRow = (uint32_t)(wn * 32 + (lane & 15)) * 144u + ((lane >> 4) & 1) * 16u;

    issue(0); issue(1);

    for (int c = 0; c < NC; c++) {
        int st = c - (c / 3) * 3;
        mbar_wait(sb + MB_OFF + (uint32_t)st * 8u, (uint32_t)((c / 3) & 1));
        __syncthreads();                       // stage (c-1)%3 fully consumed
        issue(c + 2);                          // refill stage (c+2)%3 == (c-1)%3
        const uint32_t Ahs = sb + AHO(st), Als = sb + ALO(st);
        const uint32_t Bhs = sb + BHO(st), Bls = sb + BLO(st);

        uint32_t qacc[8][2];                   // fp16x2 correction accumulators
        #pragma unroll
        for (int i = 0; i < 8; i++) { qacc[i][0] = 0u; qacc[i][1] = 0u; }

        #pragma unroll
        for (int ks = 0; ks < 4; ks++) {
            uint32_t A[2][4], AL[2][4], Q0[4], Q1[4], R0[4], R1[4];
            const uint32_t ao = aRow + (uint32_t)ks * (16u * 272u);
            const uint32_t bo = bRow + (uint32_t)ks * 32u;
            ldm_x4t(A[0],  Ahs + ao);
            ldm_x4t(A[1],  Ahs + ao + 32u);
            ldm_x4t(AL[0], Als + ao);
            ldm_x4t(AL[1], Als + ao + 32u);
            ldm_x4(Q0, Bhs + bo);
            ldm_x4(Q1, Bhs + bo + 16u * 144u);
            ldm_x4(R0, Bls + bo);
            ldm_x4(R1, Bls + bo + 16u * 144u);
            mma8f(&acc[0],  A,  Q0, Q1);       // Ah*Bh  (fp32 acc)
            mma8h(&qacc[0], AL, Q0, Q1);       // Al*Bh  (fp16 acc)
            mma8h(&qacc[0], A,  R0, R1);       // Ah*Bl  (fp16 acc)
        }
        // flush fp16 correction accumulators into fp32 (caps f16 accumulation at K=64)
        #pragma unroll
        for (int i = 0; i < 8; i++) {
            float2 lo = __half22float2(*(__half2*)&qacc[i][0]);
            float2 hi = __half22float2(*(__half2*)&qacc[i][1]);
            acc[i][0] += lo.x; acc[i][1] += lo.y;
            acc[i][2] += hi.x; acc[i][3] += hi.y;
        }
    }
    __syncthreads();

    // ---- epilogue: relu, stage through smem [128 co][132 m] ----
    float* sf = (float*)smem;
    #pragma unroll
    for (int i = 0; i < 2; i++) {
        #pragma unroll
        for (int j = 0; j < 4; j++) {
            int m  = wm * 32 + i * 16 + (lane >> 2);
            int co = wn * 32 + j * 8 + ((lane & 3) << 1);
            const float* a = acc[i*4+j];
            sf[co * 132 + m]           = fmaxf(a[0], 0.f);
            sf[(co + 1) * 132 + m]     = fmaxf(a[1], 0.f);
            sf[co * 132 + m + 8]       = fmaxf(a[2], 0.f);
            sf[(co + 1) * 132 + m + 8] = fmaxf(a[3], 0.f);
        }
    }
    __syncthreads();
    for (int idx = tid; idx < 128 * 128; idx += 512) {
        int co_l = idx >> 7, ml = idx & 127;
        int m_g = mt * 128 + ml;
        int n = m_g / 50;
        int p = m_g - n * 50;
        if (p < 49) {
            float v = sf[co_l * 132 + ml];
            int co_g = nt * 128 + co_l;
            if (P == 1) {
                size_t o = ((size_t)(n * 1024 + co_g)) * 56 + p;
                __half hh = __float2half(v);
                H16[o]  = hh;
                H16L[o] = __float2half(v - __half2float(hh));
            } else {
                d_out[O_EMB + ((size_t)(n * 1024 + co_g)) * 49 + p] = v;
            }
        }
    }
}

// ---------------- avg pool ----------------
__global__ void flat_kernel(const float* __restrict__ emb) {
    int n = blockIdx.x;
    for (int co = threadIdx.x; co < 1024; co += 256) {
        const float* e = emb + ((size_t)n * 1024 + co) * 49;
        float s = 0.f;
        #pragma unroll
        for (int p = 0; p < 49; p++) s += e[p];
        g_flat[(size_t)n * 1024 + co] = s / 49.0f;
    }
}

// ---------------- head GEMMs ----------------
__global__ void head_kernel(const float* __restrict__ cls_w, const float* __restrict__ cls_b,
                            const float* __restrict__ reg_w, const float* __restrict__ reg_b,
                            float* __restrict__ d_out) {
    int n = blockIdx.x;
    int w = threadIdx.x >> 5, lane = threadIdx.x & 31;
    const float* f = g_flat + (size_t)n * 1024;
    for (int o = w; o < 45; o += 8) {
        const float* wr; float bias;
        if (o < NCLS) { wr = cls_w + (size_t)o * 1024; bias = cls_b[o]; }
        else          { wr = reg_w + (size_t)(o - NCLS) * 1024; bias = reg_b[o - NCLS]; }
        float acc = 0.f;
        for (int k = lane; k < 1024; k += 32) acc += f[k] * wr[k];
        #pragma unroll
        for (int d = 16; d; d >>= 1) acc += __shfl_xor_sync(0xffffffffu, acc, d);
        if (lane == 0) {
            float v = acc + bias;
            if (o < NCLS) { g_cls[n * NCLS + o] = v; d_out[O_CLS + n * NCLS + o] = v; }
            else { g_reg[n * 36 + (o - NCLS)] = v; d_out[O_REG + n * 36 + (o - NCLS)] = v; }
        }
    }
}

// ---------------- softmax + box decode + clip ----------------
__global__ void decode_kernel(const float* __restrict__ proposals) {
    int n = blockIdx.x; int lane = threadIdx.x;
    float logit = (lane < NCLS) ? g_cls[n * NCLS + lane] : -INFINITY;
    float m = logit;
    #pragma unroll
    for (int d = 16; d; d >>= 1) m = fmaxf(m, __shfl_xor_sync(0xffffffffu, m, d));
    float e = (lane < NCLS) ? expf(logit - m) : 0.f;
    float s = e;
    #pragma unroll
    for (int d = 16; d; d >>= 1) s += __shfl_xor_sync(0xffffffffu, s, d);
    if (lane < NCLS) {
        g_scores[n * NCLS + lane] = e / s;
        const float* pr = proposals + (size_t)n * 4;
        float pw = pr[2] - pr[0], ph = pr[3] - pr[1];
        float pcx = pr[0] + 0.5f * pw, pcy = pr[1] + 0.5f * ph;
        const float* rr = g_reg + n * 36 + lane * 4;
        float dx = rr[0] / 10.0f, dy = rr[1] / 10.0f;
        float dw = fminf(rr[2] / 5.0f, 4.135166556742356f);
        float dh = fminf(rr[3] / 5.0f, 4.135166556742356f);
        float ncx = dx * pw + pcx, ncy = dy * ph + pcy;
        float nw = expf(dw) * pw, nh = expf(dh) * ph;
        float b0 = fminf(fmaxf(ncx - 0.5f * nw, 0.f), IMGW);
        float b1 = fminf(fmaxf(ncy - 0.5f * nh, 0.f), IMGH);
        float b2 = fminf(fmaxf(ncx + 0.5f * nw, 0.f), IMGW);
        float b3 = fminf(fmaxf(ncy + 0.5f * nh, 0.f), IMGH);
        float* bp = g_boxes + (size_t)(n * NCLS + lane) * 4;
        bp[0] = b0; bp[1] = b1; bp[2] = b2; bp[3] = b3;
    }
}

// ---------------- per-image: filter -> sort(4096) -> NMS(512) -> top-100 ----------------
__global__ void __launch_bounds__(512) nms_kernel(float* __restrict__ d_out) {
    __shared__ float skey[4096];
    __shared__ int   sidx[4096];
    __shared__ float sbox[PRE_K * 4];
    __shared__ int   skeep[PRE_K];
    __shared__ int   swsum[16];

    int img = blockIdx.x; int tid = threadIdx.x;

    for (int j = tid; j < 4096; j += 512) {
        int p = j >> 3, c = (j & 7) + 1;
        int n = img * 512 + p;
        float s = g_scores[n * NCLS + c];
        const float* bb = g_boxes + (size_t)(n * NCLS + c) * 4;
        bool valid = (s > 0.05f) && ((bb[2] - bb[0]) >= 0.01f) && ((bb[3] - bb[1]) >= 0.01f);
        skey[j] = valid ? s : -INFINITY;
        sidx[j] = j;
    }
    __syncthreads();

    for (int k = 2; k <= 4096; k <<= 1) {
        for (int j2 = k >> 1; j2 > 0; j2 >>= 1) {
            for (int i = tid; i < 4096; i += 512) {
                int ixj = i ^ j2;
                if (ixj > i) {
                    float ka = skey[i], kb = skey[ixj];
                    int ia = sidx[i], ib = sidx[ixj];
                    bool a_first = (ka > kb) || (ka == kb && ia < ib);
                    bool up = ((i & k) == 0);
                    if (up ? !a_first : a_first) {
                        skey[i] = kb; skey[ixj] = ka;
                        sidx[i] = ib; sidx[ixj] = ia;
                    }
                }
            }
            __syncthreads();
        }
    }

    if (tid < PRE_K) {
        float s = skey[tid];
        int j = sidx[tid];
        int p = j >> 3, c = (j & 7) + 1;
        int n = img * 512 + p;
        const float* bb = g_boxes + (size_t)(n * NCLS + c) * 4;
        float off = 641.0f * (float)c;
        sbox[tid * 4 + 0] = bb[0] + off;
        sbox[tid * 4 + 1] = bb[1] + off;
        sbox[tid * 4 + 2] = bb[2] + off;
        sbox[tid * 4 + 3] = bb[3] + off;
        skeep[tid] = (s != -INFINITY) ? 1 : 0;
    }
    __syncthreads();

    for (int i = 0; i < PRE_K; i++) {
        if (skeep[i]) {
            int j = tid;
            if (j > i && skeep[j]) {
                float ax0 = sbox[i*4], ay0 = sbox[i*4+1], ax1 = sbox[i*4+2], ay1 = sbox[i*4+3];
                float bx0 = sbox[j*4], by0 = sbox[j*4+1], bx1 = sbox[j*4+2], by1 = sbox[j*4+3];
                float areaA = (ax1 - ax0) * (ay1 - ay0);
                float areaB = (bx1 - bx0) * (by1 - by0);
                float iw = fmaxf(fminf(ax1, bx1) - fmaxf(ax0, bx0), 0.f);
                float ih = fmaxf(fminf(ay1, by1) - fmaxf(ay0, by0), 0.f);
                float inter = iw * ih;
                float iou = inter / fmaxf(areaA + areaB - inter, 1e-8f);
                if (iou > 0.5f) skeep[j] = 0;
            }
        }
        __syncthreads();
    }

    int keepflag = (tid < PRE_K) ? skeep[tid] : 0;
    unsigned mask = __ballot_sync(0xffffffffu, keepflag != 0);
    int lane = tid & 31, wid = tid >> 5;
    if (lane == 0) swsum[wid] = __popc(mask);
    __syncthreads();
    int base = 0;
    for (int w = 0; w < wid; w++) base += swsum[w];
    int rank = base + __popc(mask & ((1u << lane) - 1u));

    float* dbx = d_out + O_BOX + (size_t)img * DETS * 4;
    float* dsc = d_out + O_SCO + (size_t)img * DETS;
    float* dlb = d_out + O_LAB + (size_t)img * DETS;
    float* dvl = d_out + O_VAL + (size_t)img * DETS;
    for (int i = tid; i < DETS; i += 512) {
        dbx[i*4+0] = 0.f; dbx[i*4+1] = 0.f; dbx[i*4+2] = 0.f; dbx[i*4+3] = 0.f;
        dsc[i] = 0.f; dlb[i] = 0.f; dvl[i] = 0.f;
    }
    __syncthreads();
    if (keepflag && rank < DETS) {
        int j = sidx[tid];
        int p = j >> 3, c = (j & 7) + 1;
        int n = img * 512 + p;
        const float* bb = g_boxes + (size_t)(n * NCLS + c) * 4;
        dbx[rank*4+0] = bb[0]; dbx[rank*4+1] = bb[1];
        dbx[rank*4+2] = bb[2]; dbx[rank*4+3] = bb[3];
        dsc[rank] = skey[tid];
        dlb[rank] = (float)c;
        dvl[rank] = 1.0f;
    }
}

// ---------------- launch ----------------
extern "C" void kernel_launch(void* const* d_in, const int* in_sizes, int n_in,
                              void* d_out, int out_size) {
    const float* feats     = (const float*)d_in[0];
    const float* proposals = (const float*)d_in[1];
    const float* w1        = (const float*)d_in[2];
    const float* w2        = (const float*)d_in[3];
    const float* wd        = (const float*)d_in[4];
    const float* cls_w     = (const float*)d_in[5];
    const float* cls_b     = (const float*)d_in[6];
    const float* reg_w     = (const float*)d_in[7];
    const float* reg_b     = (const float*)d_in[8];
    float* out = (float*)d_out;

    cudaFuncSetAttribute(gemm_conv<1>, cudaFuncAttributeMaxDynamicSharedMemorySize, GSMEM);
    cudaFuncSetAttribute(gemm_conv<2>, cudaFuncAttributeMaxDynamicSharedMemorySize, GSMEM);

    cvt_x16<<<(int)((XN + 255) / 256), 256>>>(feats);
    cvt_w1h<<<(int)(((size_t)1024*4608 + 255) / 256), 256>>>(w1);
    cvt_wbh<<<(int)(((size_t)1024*9728 + 255) / 256), 256>>>(w2, wd);
    init_mask<<<1, 256>>>();

    im2col_kernel<1><<<4608 * 4, 256>>>();
    gemm_conv<1><<<dim3(8, 400), 512, GSMEM>>>(out);

    im2col_kernel<2><<<9728 * 4, 256>>>();
    gemm_conv<2><<<dim3(8, 400), 512, GSMEM>>>(out);

    flat_kernel<<<NSAMP, 256>>>(out + O_EMB);
    head_kernel<<<NSAMP, 256>>>(cls_w, cls_b, reg_w, reg_b, out);
    decode_kernel<<<NSAMP, 32>>>(proposals);
    nms_kernel<<<2, 512>>>(out);
}